// round 12
// baseline (speedup 1.0000x reference)
#include <cuda_runtime.h>

// GroupConv2D: B=32, H=W=56, Cin=Cout=256, G=8 (32 ch/group), 3x3 SAME, NHWC/HWIO, fp32.
//
// Strategy: direct conv, fma-pipe bound. Per block: (batch b, group g, 8 rows x 56 cols).
// SMEM: input tile 10x58x32 (channel-padded to 36 for bank-conflict-free LDS.128),
//       group weights 9x32x32 (cout contiguous -> LDS.64 gives f32x2 weight pairs).
// Per thread: 7 pixels x 8 couts, accumulated in f32x2 pairs via fma.rn.f32x2 (FFMA2).

#define GRP   8
#define BATCH 32
#define HH    56
#define WW    56
#define CIN   256
#define COUT  256
#define CG    32          // channels per group (in and out)
#define TH    8           // output rows per block
#define ROWS  (TH + 2)    // 10 input rows in tile
#define COLSX (WW + 2)    // 58 input cols in tile
#define PADC  36          // padded channel stride in SMEM (conflict avoidance, 16B aligned)

#define SIN_FLOATS (ROWS * COLSX * PADC)   // 20880
#define SW_FLOATS  (9 * CG * CG)           // 9216
#define SMEM_BYTES ((SIN_FLOATS + SW_FLOATS) * 4)   // 120384 B

__global__ __launch_bounds__(256, 1)
void gconv2d_kernel(const float* __restrict__ gin,
                    const float* __restrict__ gker,
                    const float* __restrict__ gbias,
                    float* __restrict__ gout)
{
    extern __shared__ float smem[];
    float* sin = smem;                 // [ROWS][COLSX][PADC]
    float* sw  = smem + SIN_FLOATS;    // [9][CG cin][CG cout]

    const int g   = blockIdx.x;        // group
    const int y0  = blockIdx.y * TH;   // first output row
    const int b   = blockIdx.z;        // batch
    const int tid = threadIdx.x;

    // ---- Load group weights into SMEM: 9*32 cin-rows x 8 float4 of couts ----
    #pragma unroll 1
    for (int idx = tid; idx < 9 * CG * (CG / 4); idx += 256) {
        int cik = idx >> 3;            // kpos*32 + ci, 0..287
        int c4  = idx & 7;             // cout float4 index
        float4 v = *reinterpret_cast<const float4*>(gker + cik * COUT + g * CG + c4 * 4);
        *reinterpret_cast<float4*>(sw + cik * CG + c4 * 4) = v;
    }

    // ---- Load input tile (10 rows x 58 cols x 32 ch) with zero padding ----
    #pragma unroll 1
    for (int idx = tid; idx < ROWS * COLSX * (CG / 4); idx += 256) {
        int r   = idx / (COLSX * 8);
        int rem = idx - r * (COLSX * 8);
        int xx  = rem >> 3;
        int c4  = rem & 7;
        int gy  = y0 - 1 + r;
        int gx  = xx - 1;
        float4 v = make_float4(0.f, 0.f, 0.f, 0.f);
        if ((unsigned)gy < (unsigned)HH && (unsigned)gx < (unsigned)WW) {
            v = *reinterpret_cast<const float4*>(
                gin + (((size_t)b * HH + gy) * WW + gx) * CIN + g * CG + c4 * 4);
        }
        *reinterpret_cast<float4*>(sin + (r * COLSX + xx) * PADC + c4 * 4) = v;
    }
    __syncthreads();

    // ---- Thread mapping: cc (cout chunk of 8), ry (row), tx (7-pixel x-chunk) ----
    const int cc = tid >> 6;           // 0..3  (constant within a warp -> weight broadcast)
    const int ry = (tid >> 3) & 7;     // 0..7
    const int tx = tid & 7;            // 0..7
    const int c0 = cc * 8;
    const int x0 = tx * 7;

    // Accumulators: 7 pixels x 4 f32x2 pairs (8 couts), init with bias pairs.
    unsigned long long acc[7][4];
    #pragma unroll
    for (int j = 0; j < 4; ++j) {
        float bx = gbias[g * CG + c0 + 2 * j];
        float by = gbias[g * CG + c0 + 2 * j + 1];
        unsigned long long bb;
        asm("mov.b64 %0, {%1, %2};" : "=l"(bb) : "f"(bx), "f"(by));
        #pragma unroll
        for (int p = 0; p < 7; ++p) acc[p][j] = bb;
    }

    #pragma unroll
    for (int kh = 0; kh < 3; ++kh) {
        const float* srow = sin + (ry + kh) * (COLSX * PADC);
        #pragma unroll
        for (int kw = 0; kw < 3; ++kw) {
            const float* sbase = srow + (x0 + kw) * PADC;
            const float* wbase = sw + (kh * 3 + kw) * (CG * CG) + c0;
            #pragma unroll 1
            for (int ci4 = 0; ci4 < 8; ++ci4) {
                // 7 pixels x 4 cin via LDS.128 (conflict-free thanks to PADC=36)
                float4 iv[7];
                #pragma unroll
                for (int p = 0; p < 7; ++p)
                    iv[p] = *reinterpret_cast<const float4*>(sbase + p * PADC + ci4 * 4);

                #pragma unroll
                for (int i = 0; i < 4; ++i) {
                    // 4 weight pairs (8 couts) for this cin: warp-uniform LDS.64
                    unsigned long long w[4];
                    #pragma unroll
                    for (int j = 0; j < 4; ++j)
                        w[j] = *reinterpret_cast<const unsigned long long*>(
                            wbase + (ci4 * 4 + i) * CG + 2 * j);

                    #pragma unroll
                    for (int p = 0; p < 7; ++p) {
                        float v = (i == 0) ? iv[p].x : (i == 1) ? iv[p].y
                                : (i == 2) ? iv[p].z : iv[p].w;
                        unsigned long long vv;
                        asm("mov.b64 %0, {%1, %1};" : "=l"(vv) : "f"(v));
                        #pragma unroll
                        for (int j = 0; j < 4; ++j)
                            asm("fma.rn.f32x2 %0, %1, %2, %0;"
                                : "+l"(acc[p][j]) : "l"(vv), "l"(w[j]));
                    }
                }
            }
        }
    }

    // ---- Store: 7 pixels x 8 contiguous couts ----
    float* obase = gout + (((size_t)b * HH + (y0 + ry)) * WW + x0) * COUT + g * CG + c0;
    #pragma unroll
    for (int p = 0; p < 7; ++p) {
        float* o = obase + p * COUT;
        #pragma unroll
        for (int j = 0; j < 4; ++j) {
            float lo, hi;
            asm("mov.b64 {%0, %1}, %2;" : "=f"(lo), "=f"(hi) : "l"(acc[p][j]));
            *reinterpret_cast<float2*>(o + 2 * j) = make_float2(lo, hi);
        }
    }
}

extern "C" void kernel_launch(void* const* d_in, const int* in_sizes, int n_in,
                              void* d_out, int out_size)
{
    const float* gin   = (const float*)d_in[0];   // [32,56,56,256] fp32
    const float* gker  = (const float*)d_in[1];   // [3,3,32,256]   fp32
    const float* gbias = (const float*)d_in[2];   // [256]          fp32
    float* gout = (float*)d_out;                  // [32,56,56,256] fp32

    cudaFuncSetAttribute(gconv2d_kernel,
                         cudaFuncAttributeMaxDynamicSharedMemorySize, SMEM_BYTES);

    dim3 grid(GRP, HH / TH, BATCH);   // (8, 7, 32) = 1792 blocks
    gconv2d_kernel<<<grid, 256, SMEM_BYTES>>>(gin, gker, gbias, gout);
}

// round 13
// speedup vs baseline: 1.0003x; 1.0003x over previous
#include <cuda_runtime.h>

// GroupConv2D: B=32, H=W=56, Cin=Cout=256, G=8 (32 ch/group), 3x3 SAME, NHWC/HWIO, fp32.
//
// Strategy: direct conv, fma-pipe bound. Per block: (batch b, group g, 8 rows x 56 cols).
// SMEM: input tile 10x58x32 (channel-padded to 36 for bank-conflict-free LDS.128),
//       group weights 9x32x32 (cout contiguous -> LDS.64 gives f32x2 weight pairs).
// Per thread: 7 pixels x 8 couts, accumulated in f32x2 pairs via fma.rn.f32x2 (FFMA2).

#define GRP   8
#define BATCH 32
#define HH    56
#define WW    56
#define CIN   256
#define COUT  256
#define CG    32          // channels per group (in and out)
#define TH    8           // output rows per block
#define ROWS  (TH + 2)    // 10 input rows in tile
#define COLSX (WW + 2)    // 58 input cols in tile
#define PADC  36          // padded channel stride in SMEM (conflict avoidance, 16B aligned)

#define SIN_FLOATS (ROWS * COLSX * PADC)   // 20880
#define SW_FLOATS  (9 * CG * CG)           // 9216
#define SMEM_BYTES ((SIN_FLOATS + SW_FLOATS) * 4)   // 120384 B

__global__ __launch_bounds__(256, 1)
void gconv2d_kernel(const float* __restrict__ gin,
                    const float* __restrict__ gker,
                    const float* __restrict__ gbias,
                    float* __restrict__ gout)
{
    extern __shared__ float smem[];
    float* sin = smem;                 // [ROWS][COLSX][PADC]
    float* sw  = smem + SIN_FLOATS;    // [9][CG cin][CG cout]

    const int g   = blockIdx.x;        // group
    const int y0  = blockIdx.y * TH;   // first output row
    const int b   = blockIdx.z;        // batch
    const int tid = threadIdx.x;

    // ---- Load group weights into SMEM: 9*32 cin-rows x 8 float4 of couts ----
    #pragma unroll 1
    for (int idx = tid; idx < 9 * CG * (CG / 4); idx += 256) {
        int cik = idx >> 3;            // kpos*32 + ci, 0..287
        int c4  = idx & 7;             // cout float4 index
        float4 v = *reinterpret_cast<const float4*>(gker + cik * COUT + g * CG + c4 * 4);
        *reinterpret_cast<float4*>(sw + cik * CG + c4 * 4) = v;
    }

    // ---- Load input tile (10 rows x 58 cols x 32 ch) with zero padding ----
    #pragma unroll 1
    for (int idx = tid; idx < ROWS * COLSX * (CG / 4); idx += 256) {
        int r   = idx / (COLSX * 8);
        int rem = idx - r * (COLSX * 8);
        int xx  = rem >> 3;
        int c4  = rem & 7;
        int gy  = y0 - 1 + r;
        int gx  = xx - 1;
        float4 v = make_float4(0.f, 0.f, 0.f, 0.f);
        if ((unsigned)gy < (unsigned)HH && (unsigned)gx < (unsigned)WW) {
            v = *reinterpret_cast<const float4*>(
                gin + (((size_t)b * HH + gy) * WW + gx) * CIN + g * CG + c4 * 4);
        }
        *reinterpret_cast<float4*>(sin + (r * COLSX + xx) * PADC + c4 * 4) = v;
    }
    __syncthreads();

    // ---- Thread mapping: cc (cout chunk of 8), ry (row), tx (7-pixel x-chunk) ----
    const int cc = tid >> 6;           // 0..3  (constant within a warp -> weight broadcast)
    const int ry = (tid >> 3) & 7;     // 0..7
    const int tx = tid & 7;            // 0..7
    const int c0 = cc * 8;
    const int x0 = tx * 7;

    // Accumulators: 7 pixels x 4 f32x2 pairs (8 couts), init with bias pairs.
    unsigned long long acc[7][4];
    #pragma unroll
    for (int j = 0; j < 4; ++j) {
        float bx = gbias[g * CG + c0 + 2 * j];
        float by = gbias[g * CG + c0 + 2 * j + 1];
        unsigned long long bb;
        asm("mov.b64 %0, {%1, %2};" : "=l"(bb) : "f"(bx), "f"(by));
        #pragma unroll
        for (int p = 0; p < 7; ++p) acc[p][j] = bb;
    }

    #pragma unroll
    for (int kh = 0; kh < 3; ++kh) {
        const float* srow = sin + (ry + kh) * (COLSX * PADC);
        #pragma unroll
        for (int kw = 0; kw < 3; ++kw) {
            const float* sbase = srow + (x0 + kw) * PADC;
            const float* wbase = sw + (kh * 3 + kw) * (CG * CG) + c0;
            #pragma unroll 1
            for (int ci4 = 0; ci4 < 8; ++ci4) {
                // 7 pixels x 4 cin via LDS.128 (conflict-free thanks to PADC=36)
                float4 iv[7];
                #pragma unroll
                for (int p = 0; p < 7; ++p)
                    iv[p] = *reinterpret_cast<const float4*>(sbase + p * PADC + ci4 * 4);

                #pragma unroll
                for (int i = 0; i < 4; ++i) {
                    // 4 weight pairs (8 couts) for this cin: warp-uniform LDS.64
                    unsigned long long w[4];
                    #pragma unroll
                    for (int j = 0; j < 4; ++j)
                        w[j] = *reinterpret_cast<const unsigned long long*>(
                            wbase + (ci4 * 4 + i) * CG + 2 * j);

                    #pragma unroll
                    for (int p = 0; p < 7; ++p) {
                        float v = (i == 0) ? iv[p].x : (i == 1) ? iv[p].y
                                : (i == 2) ? iv[p].z : iv[p].w;
                        unsigned long long vv;
                        asm("mov.b64 %0, {%1, %1};" : "=l"(vv) : "f"(v));
                        #pragma unroll
                        for (int j = 0; j < 4; ++j)
                            asm("fma.rn.f32x2 %0, %1, %2, %0;"
                                : "+l"(acc[p][j]) : "l"(vv), "l"(w[j]));
                    }
                }
            }
        }
    }

    // ---- Store: 7 pixels x 8 contiguous couts ----
    float* obase = gout + (((size_t)b * HH + (y0 + ry)) * WW + x0) * COUT + g * CG + c0;
    #pragma unroll
    for (int p = 0; p < 7; ++p) {
        float* o = obase + p * COUT;
        #pragma unroll
        for (int j = 0; j < 4; ++j) {
            float lo, hi;
            asm("mov.b64 {%0, %1}, %2;" : "=f"(lo), "=f"(hi) : "l"(acc[p][j]));
            *reinterpret_cast<float2*>(o + 2 * j) = make_float2(lo, hi);
        }
    }
}

extern "C" void kernel_launch(void* const* d_in, const int* in_sizes, int n_in,
                              void* d_out, int out_size)
{
    const float* gin   = (const float*)d_in[0];   // [32,56,56,256] fp32
    const float* gker  = (const float*)d_in[1];   // [3,3,32,256]   fp32
    const float* gbias = (const float*)d_in[2];   // [256]          fp32
    float* gout = (float*)d_out;                  // [32,56,56,256] fp32

    cudaFuncSetAttribute(gconv2d_kernel,
                         cudaFuncAttributeMaxDynamicSharedMemorySize, SMEM_BYTES);

    dim3 grid(GRP, HH / TH, BATCH);   // (8, 7, 32) = 1792 blocks
    gconv2d_kernel<<<grid, 256, SMEM_BYTES>>>(gin, gker, gbias, gout);
}

// round 14
// speedup vs baseline: 1.0013x; 1.0010x over previous
#include <cuda_runtime.h>

// GroupConv2D: B=32, H=W=56, Cin=Cout=256, G=8 (32 ch/group), 3x3 SAME, NHWC/HWIO, fp32.
//
// Strategy: direct conv, fma-pipe bound. Per block: (batch b, group g, 8 rows x 56 cols).
// SMEM: input tile 10x58x32 (channel-padded to 36 for bank-conflict-free LDS.128),
//       group weights 9x32x32 (cout contiguous -> LDS.64 gives f32x2 weight pairs).
// Per thread: 7 pixels x 8 couts, accumulated in f32x2 pairs via fma.rn.f32x2 (FFMA2).

#define GRP   8
#define BATCH 32
#define HH    56
#define WW    56
#define CIN   256
#define COUT  256
#define CG    32          // channels per group (in and out)
#define TH    8           // output rows per block
#define ROWS  (TH + 2)    // 10 input rows in tile
#define COLSX (WW + 2)    // 58 input cols in tile
#define PADC  36          // padded channel stride in SMEM (conflict avoidance, 16B aligned)

#define SIN_FLOATS (ROWS * COLSX * PADC)   // 20880
#define SW_FLOATS  (9 * CG * CG)           // 9216
#define SMEM_BYTES ((SIN_FLOATS + SW_FLOATS) * 4)   // 120384 B

__global__ __launch_bounds__(256, 1)
void gconv2d_kernel(const float* __restrict__ gin,
                    const float* __restrict__ gker,
                    const float* __restrict__ gbias,
                    float* __restrict__ gout)
{
    extern __shared__ float smem[];
    float* sin = smem;                 // [ROWS][COLSX][PADC]
    float* sw  = smem + SIN_FLOATS;    // [9][CG cin][CG cout]

    const int g   = blockIdx.x;        // group
    const int y0  = blockIdx.y * TH;   // first output row
    const int b   = blockIdx.z;        // batch
    const int tid = threadIdx.x;

    // ---- Load group weights into SMEM: 9*32 cin-rows x 8 float4 of couts ----
    #pragma unroll 1
    for (int idx = tid; idx < 9 * CG * (CG / 4); idx += 256) {
        int cik = idx >> 3;            // kpos*32 + ci, 0..287
        int c4  = idx & 7;             // cout float4 index
        float4 v = *reinterpret_cast<const float4*>(gker + cik * COUT + g * CG + c4 * 4);
        *reinterpret_cast<float4*>(sw + cik * CG + c4 * 4) = v;
    }

    // ---- Load input tile (10 rows x 58 cols x 32 ch) with zero padding ----
    #pragma unroll 1
    for (int idx = tid; idx < ROWS * COLSX * (CG / 4); idx += 256) {
        int r   = idx / (COLSX * 8);
        int rem = idx - r * (COLSX * 8);
        int xx  = rem >> 3;
        int c4  = rem & 7;
        int gy  = y0 - 1 + r;
        int gx  = xx - 1;
        float4 v = make_float4(0.f, 0.f, 0.f, 0.f);
        if ((unsigned)gy < (unsigned)HH && (unsigned)gx < (unsigned)WW) {
            v = *reinterpret_cast<const float4*>(
                gin + (((size_t)b * HH + gy) * WW + gx) * CIN + g * CG + c4 * 4);
        }
        *reinterpret_cast<float4*>(sin + (r * COLSX + xx) * PADC + c4 * 4) = v;
    }
    __syncthreads();

    // ---- Thread mapping: cc (cout chunk of 8), ry (row), tx (7-pixel x-chunk) ----
    const int cc = tid >> 6;           // 0..3  (constant within a warp -> weight broadcast)
    const int ry = (tid >> 3) & 7;     // 0..7
    const int tx = tid & 7;            // 0..7
    const int c0 = cc * 8;
    const int x0 = tx * 7;

    // Accumulators: 7 pixels x 4 f32x2 pairs (8 couts), init with bias pairs.
    unsigned long long acc[7][4];
    #pragma unroll
    for (int j = 0; j < 4; ++j) {
        float bx = gbias[g * CG + c0 + 2 * j];
        float by = gbias[g * CG + c0 + 2 * j + 1];
        unsigned long long bb;
        asm("mov.b64 %0, {%1, %2};" : "=l"(bb) : "f"(bx), "f"(by));
        #pragma unroll
        for (int p = 0; p < 7; ++p) acc[p][j] = bb;
    }

    #pragma unroll
    for (int kh = 0; kh < 3; ++kh) {
        const float* srow = sin + (ry + kh) * (COLSX * PADC);
        #pragma unroll
        for (int kw = 0; kw < 3; ++kw) {
            const float* sbase = srow + (x0 + kw) * PADC;
            const float* wbase = sw + (kh * 3 + kw) * (CG * CG) + c0;
            #pragma unroll 1
            for (int ci4 = 0; ci4 < 8; ++ci4) {
                // 7 pixels x 4 cin via LDS.128 (conflict-free thanks to PADC=36)
                float4 iv[7];
                #pragma unroll
                for (int p = 0; p < 7; ++p)
                    iv[p] = *reinterpret_cast<const float4*>(sbase + p * PADC + ci4 * 4);

                #pragma unroll
                for (int i = 0; i < 4; ++i) {
                    // 4 weight pairs (8 couts) for this cin: warp-uniform LDS.64
                    unsigned long long w[4];
                    #pragma unroll
                    for (int j = 0; j < 4; ++j)
                        w[j] = *reinterpret_cast<const unsigned long long*>(
                            wbase + (ci4 * 4 + i) * CG + 2 * j);

                    #pragma unroll
                    for (int p = 0; p < 7; ++p) {
                        float v = (i == 0) ? iv[p].x : (i == 1) ? iv[p].y
                                : (i == 2) ? iv[p].z : iv[p].w;
                        unsigned long long vv;
                        asm("mov.b64 %0, {%1, %1};" : "=l"(vv) : "f"(v));
                        #pragma unroll
                        for (int j = 0; j < 4; ++j)
                            asm("fma.rn.f32x2 %0, %1, %2, %0;"
                                : "+l"(acc[p][j]) : "l"(vv), "l"(w[j]));
                    }
                }
            }
        }
    }

    // ---- Store: 7 pixels x 8 contiguous couts ----
    float* obase = gout + (((size_t)b * HH + (y0 + ry)) * WW + x0) * COUT + g * CG + c0;
    #pragma unroll
    for (int p = 0; p < 7; ++p) {
        float* o = obase + p * COUT;
        #pragma unroll
        for (int j = 0; j < 4; ++j) {
            float lo, hi;
            asm("mov.b64 {%0, %1}, %2;" : "=f"(lo), "=f"(hi) : "l"(acc[p][j]));
            *reinterpret_cast<float2*>(o + 2 * j) = make_float2(lo, hi);
        }
    }
}

extern "C" void kernel_launch(void* const* d_in, const int* in_sizes, int n_in,
                              void* d_out, int out_size)
{
    const float* gin   = (const float*)d_in[0];   // [32,56,56,256] fp32
    const float* gker  = (const float*)d_in[1];   // [3,3,32,256]   fp32
    const float* gbias = (const float*)d_in[2];   // [256]          fp32
    float* gout = (float*)d_out;                  // [32,56,56,256] fp32

    cudaFuncSetAttribute(gconv2d_kernel,
                         cudaFuncAttributeMaxDynamicSharedMemorySize, SMEM_BYTES);

    dim3 grid(GRP, HH / TH, BATCH);   // (8, 7, 32) = 1792 blocks
    gconv2d_kernel<<<grid, 256, SMEM_BYTES>>>(gin, gker, gbias, gout);
}